// round 3
// baseline (speedup 1.0000x reference)
#include <cuda_runtime.h>
#include <math.h>

#define UNQ   256
#define DIM   1024
#define NT    16
#define BATCH 16384

static __device__ float g_X[UNQ*DIM];
static __device__ float g_H[NT*UNQ*DIM];
static __device__ float g_Y[NT*UNQ*DIM];
static __device__ int   g_cnt[NT];
static __device__ int   g_rows[NT*UNQ];
static __device__ float g_gate[NT*UNQ];
static __device__ int   g_pairs[UNQ*4];
static __device__ float g_table[UNQ*11];

__device__ __forceinline__ float gelu_f(float x) {
    return 0.5f * x * (1.0f + erff(x * 0.70710678118654752f));
}

__device__ __forceinline__ float block_reduce_sum_256(float v, float* red) {
    int tid = threadIdx.x;
    red[tid] = v;
    __syncthreads();
    #pragma unroll
    for (int s = 128; s > 0; s >>= 1) {
        if (tid < s) red[tid] += red[tid + s];
        __syncthreads();
    }
    float r = red[0];
    __syncthreads();
    return r;
}

// ---------------------------------------------------------------------------
// Encode: fourier(a),fourier(b) -> @Win + bias -> LN -> GELU, for 256 uniques
// ---------------------------------------------------------------------------
__global__ void encode_kernel(const float* __restrict__ Win, const float* __restrict__ bin_,
                              const float* __restrict__ gin, const float* __restrict__ bln) {
    int u = blockIdx.x, tid = threadIdx.x;
    __shared__ float feat[32];
    __shared__ float red[256];
    if (tid < 32) {
        int which  = tid >> 4;          // 0 -> a-features, 1 -> b-features
        int idx    = tid & 15;          // [sin0..7, cos0..7]
        int fi     = idx & 7;
        int is_cos = (idx >> 3) & 1;
        int val    = which ? (u & 15) : (u >> 4);
        float xn   = (float)val * 0.39269908169872414f;   // fp32(2*pi/16), as JAX does
        float ang  = xn * exp2f((float)fi);               // exact pow2 scale
        double dd  = (double)ang;                         // accurate sin/cos regardless of fast-math
        feat[tid]  = (float)(is_cos ? cos(dd) : sin(dd));
    }
    __syncthreads();
    float v[4];
    #pragma unroll
    for (int j = 0; j < 4; ++j) {
        int d = tid + 256*j;
        float acc = bin_[d];
        #pragma unroll
        for (int f = 0; f < 32; ++f) acc += feat[f] * Win[f*DIM + d];
        v[j] = acc;
    }
    float s = block_reduce_sum_256(v[0]+v[1]+v[2]+v[3], red);
    float m = s * (1.0f/DIM);
    float s2l = 0.f;
    #pragma unroll
    for (int j = 0; j < 4; ++j) { float t = v[j]-m; s2l += t*t; }
    float s2 = block_reduce_sum_256(s2l, red);
    float rs = rsqrtf(s2*(1.0f/DIM) + 1e-5f);
    #pragma unroll
    for (int j = 0; j < 4; ++j) {
        int d = tid + 256*j;
        float y = (v[j]-m)*rs*gin[d] + bln[d];
        g_X[u*DIM + d] = gelu_f(y);
    }
}

// ---------------------------------------------------------------------------
// Router: softmax(x @ Wr) -> top-4 -> per-tile compacted (row, gate) lists
// ---------------------------------------------------------------------------
__global__ void zero_kernel() {
    if (threadIdx.x < NT) g_cnt[threadIdx.x] = 0;
}

__global__ void router_kernel(const float* __restrict__ Wr) {
    int r = blockIdx.x, tid = threadIdx.x;
    __shared__ float part[256];
    int t = tid & 15, seg = tid >> 4;
    const float* x = g_X + r*DIM;
    float p = 0.f;
    int base = seg*64;
    #pragma unroll 8
    for (int j = 0; j < 64; ++j) p += x[base+j] * Wr[(base+j)*NT + t];
    part[tid] = p;
    __syncthreads();
    if (tid < 16) {
        float lg = 0.f;
        #pragma unroll
        for (int s = 0; s < 16; ++s) lg += part[tid + (s<<4)];
        part[tid] = lg;
    }
    __syncthreads();
    if (tid == 0) {
        float lg[16], mx = -1e30f;
        #pragma unroll
        for (int i = 0; i < 16; ++i) { lg[i] = part[i]; mx = fmaxf(mx, lg[i]); }
        float pe[16], sum = 0.f;
        #pragma unroll
        for (int i = 0; i < 16; ++i) { pe[i] = expf(lg[i]-mx); sum += pe[i]; }
        float inv = 1.0f/sum;
        unsigned used = 0;
        for (int s = 0; s < 4; ++s) {
            int best = -1; float bv = -1e30f;
            #pragma unroll
            for (int i = 0; i < 16; ++i)
                if (!((used>>i)&1) && pe[i] > bv) { bv = pe[i]; best = i; }
            used |= 1u << best;
            int pos = atomicAdd(&g_cnt[best], 1);
            g_rows[best*UNQ + pos] = r;
            g_gate[best*UNQ + pos] = bv*inv;
            g_pairs[r*4 + s] = best*UNQ + pos;
        }
    }
}

// ---------------------------------------------------------------------------
// FFN GEMM: per (tile, 32-row chunk, 128-col chunk); 4x4 microtile, smem-staged.
// MODE 0: H[p] = gelu(X[row] @ W1[t] + b1[t])     (gathered rows)
// MODE 1: Y[p] = gate[p] * (H[p] @ W2[t] + b2[t]) (contiguous rows)
// ---------------------------------------------------------------------------
template<int MODE>
__global__ void ffn_kernel(const float* __restrict__ W, const float* __restrict__ bias) {
    int t  = blockIdx.z, rc = blockIdx.y, cc = blockIdx.x;
    int cnt = g_cnt[t];
    if (rc*32 >= cnt) return;

    W += (size_t)t*DIM*DIM;   // <-- per-tile expert weights (bug fix)

    __shared__ float Xs[32][32];    // [local row][k]
    __shared__ float Ws[32][128];   // [k][col]
    __shared__ int   rows_s[32];
    __shared__ float gate_s[32];

    int tid = threadIdx.x;
    if (tid < 32) {
        int idx = rc*32 + tid;
        int ci  = (idx < cnt) ? idx : (cnt-1);
        if (MODE == 0) rows_s[tid] = g_rows[t*UNQ + ci];
        else {
            rows_s[tid] = t*UNQ + rc*32 + tid;   // contiguous pair rows in g_H
            gate_s[tid] = (idx < cnt) ? g_gate[t*UNQ + idx] : 0.f;
        }
    }
    __syncthreads();

    const float* src = (MODE == 0) ? g_X : g_H;
    int rg = tid >> 5;          // 0..7  -> rows rg*4..rg*4+3
    int cg = tid & 31;          // 0..31 -> cols cg*4..cg*4+3
    int c0 = cc*128;

    float acc[4][4];
    #pragma unroll
    for (int i = 0; i < 4; ++i)
        #pragma unroll
        for (int j = 0; j < 4; ++j) acc[i][j] = 0.f;

    int li = tid >> 3, lkv = tid & 7;  // X-stage mapping: 32 rows x 8 float4

    for (int k0 = 0; k0 < DIM; k0 += 32) {
        // stage 32x32 activations (coalesced per row)
        *(float4*)&Xs[li][lkv*4] =
            *(const float4*)(src + (size_t)rows_s[li]*DIM + k0 + lkv*4);
        // stage 32x128 weights
        #pragma unroll
        for (int q = 0; q < 4; ++q) {
            int e = tid + q*256;
            int k = e >> 5, cv = e & 31;
            *(float4*)&Ws[k][cv*4] =
                *(const float4*)&W[(size_t)(k0+k)*DIM + c0 + cv*4];
        }
        __syncthreads();
        #pragma unroll
        for (int k = 0; k < 32; ++k) {
            float a0 = Xs[rg*4+0][k], a1 = Xs[rg*4+1][k];
            float a2 = Xs[rg*4+2][k], a3 = Xs[rg*4+3][k];
            float4 bv = *(const float4*)&Ws[k][cg*4];
            acc[0][0] += a0*bv.x; acc[0][1] += a0*bv.y; acc[0][2] += a0*bv.z; acc[0][3] += a0*bv.w;
            acc[1][0] += a1*bv.x; acc[1][1] += a1*bv.y; acc[1][2] += a1*bv.z; acc[1][3] += a1*bv.w;
            acc[2][0] += a2*bv.x; acc[2][1] += a2*bv.y; acc[2][2] += a2*bv.z; acc[2][3] += a2*bv.w;
            acc[3][0] += a3*bv.x; acc[3][1] += a3*bv.y; acc[3][2] += a3*bv.z; acc[3][3] += a3*bv.w;
        }
        __syncthreads();
    }

    int pbase = t*UNQ + rc*32;
    float bvals[4];
    #pragma unroll
    for (int j = 0; j < 4; ++j) bvals[j] = bias[t*DIM + c0 + cg*4 + j];

    #pragma unroll
    for (int i = 0; i < 4; ++i) {
        int lr = rg*4 + i;
        float v0 = acc[i][0]+bvals[0], v1 = acc[i][1]+bvals[1];
        float v2 = acc[i][2]+bvals[2], v3 = acc[i][3]+bvals[3];
        float4 o;
        if (MODE == 0) {
            o.x = gelu_f(v0); o.y = gelu_f(v1); o.z = gelu_f(v2); o.w = gelu_f(v3);
            *(float4*)&g_H[(size_t)(pbase+lr)*DIM + c0 + cg*4] = o;
        } else {
            float gt = gate_s[lr];
            o.x = v0*gt; o.y = v1*gt; o.z = v2*gt; o.w = v3*gt;
            *(float4*)&g_Y[(size_t)(pbase+lr)*DIM + c0 + cg*4] = o;
        }
    }
}

// ---------------------------------------------------------------------------
// Combine: x = LN(x + sum over the row's 4 gated expert outputs)
// ---------------------------------------------------------------------------
__global__ void combine_kernel(const float* __restrict__ gl, const float* __restrict__ bl) {
    int r = blockIdx.x, tid = threadIdx.x;
    __shared__ float red[256];
    int p0 = g_pairs[r*4+0], p1 = g_pairs[r*4+1];
    int p2 = g_pairs[r*4+2], p3 = g_pairs[r*4+3];
    float v[4];
    #pragma unroll
    for (int j = 0; j < 4; ++j) {
        int d = tid + 256*j;
        v[j] = g_X[r*DIM+d]
             + g_Y[(size_t)p0*DIM+d] + g_Y[(size_t)p1*DIM+d]
             + g_Y[(size_t)p2*DIM+d] + g_Y[(size_t)p3*DIM+d];
    }
    float s = block_reduce_sum_256(v[0]+v[1]+v[2]+v[3], red);
    float m = s * (1.0f/DIM);
    float s2l = 0.f;
    #pragma unroll
    for (int j = 0; j < 4; ++j) { float t = v[j]-m; s2l += t*t; }
    float s2 = block_reduce_sum_256(s2l, red);
    float rs = rsqrtf(s2*(1.0f/DIM) + 1e-5f);
    #pragma unroll
    for (int j = 0; j < 4; ++j) {
        int d = tid + 256*j;
        g_X[r*DIM+d] = (v[j]-m)*rs*gl[d] + bl[d];
    }
}

// ---------------------------------------------------------------------------
// Heads: table[u] = [gelu(x@Ws1+bs1)@Ws2+bs2 , gelu(x@Wd1+bd1)@Wd2+bd2]
// ---------------------------------------------------------------------------
__global__ void heads_kernel(const float* __restrict__ Ws1, const float* __restrict__ bs1,
                             const float* __restrict__ Ws2, const float* __restrict__ bs2,
                             const float* __restrict__ Wd1, const float* __restrict__ bd1,
                             const float* __restrict__ Wd2, const float* __restrict__ bd2) {
    int u = blockIdx.x, tid = threadIdx.x;
    __shared__ float xr[DIM];
    __shared__ float hs[512], hd[512];
    #pragma unroll
    for (int j = 0; j < 4; ++j) xr[tid+256*j] = g_X[u*DIM + tid + 256*j];
    __syncthreads();
    for (int h = tid; h < 512; h += 256) {
        float as = bs1[h], ad = bd1[h];
        #pragma unroll 4
        for (int d = 0; d < DIM; ++d) {
            float xv = xr[d];
            as += xv * Ws1[d*512 + h];
            ad += xv * Wd1[d*512 + h];
        }
        hs[h] = gelu_f(as);
        hd[h] = gelu_f(ad);
    }
    __syncthreads();
    if (tid < 5) {
        float o = bs2[tid];
        for (int k = 0; k < 512; ++k) o += hs[k]*Ws2[k*5 + tid];
        g_table[u*11 + tid] = o;
    } else if (tid < 11) {
        int j = tid - 5;
        float o = bd2[j];
        for (int k = 0; k < 512; ++k) o += hd[k]*Wd2[k*6 + j];
        g_table[u*11 + tid] = o;
    }
}

// ---------------------------------------------------------------------------
// Scatter table rows back to the full batch
// ---------------------------------------------------------------------------
__global__ void scatter_kernel(const int* __restrict__ a, const int* __restrict__ b,
                               float* __restrict__ out) {
    int idx = blockIdx.x*blockDim.x + threadIdx.x;
    if (idx >= BATCH*11) return;
    int i = idx / 11;
    int j = idx - i*11;
    int u = a[i]*16 + b[i];
    out[idx] = g_table[u*11 + j];
}

// ---------------------------------------------------------------------------
extern "C" void kernel_launch(void* const* d_in, const int* in_sizes, int n_in,
                              void* d_out, int out_size) {
    const int*   a    = (const int*)  d_in[0];
    const int*   b    = (const int*)  d_in[1];
    const float* Win  = (const float*)d_in[2];
    const float* bin_ = (const float*)d_in[3];
    const float* g_in = (const float*)d_in[4];
    const float* bln  = (const float*)d_in[5];
    const float* Wr   = (const float*)d_in[6];
    const float* W1   = (const float*)d_in[7];
    const float* b1   = (const float*)d_in[8];
    const float* W2   = (const float*)d_in[9];
    const float* b2   = (const float*)d_in[10];
    const float* g_l  = (const float*)d_in[11];
    const float* b_l  = (const float*)d_in[12];
    const float* Ws1  = (const float*)d_in[13];
    const float* bs1  = (const float*)d_in[14];
    const float* Ws2  = (const float*)d_in[15];
    const float* bs2  = (const float*)d_in[16];
    const float* Wd1  = (const float*)d_in[17];
    const float* bd1  = (const float*)d_in[18];
    const float* Wd2  = (const float*)d_in[19];
    const float* bd2  = (const float*)d_in[20];
    float* out = (float*)d_out;

    encode_kernel<<<UNQ, 256>>>(Win, bin_, g_in, bln);
    for (int l = 0; l < 3; ++l) {
        zero_kernel<<<1, 32>>>();
        router_kernel<<<UNQ, 256>>>(Wr + (size_t)l*DIM*NT);
        ffn_kernel<0><<<dim3(8, 8, 16), 256>>>(W1 + (size_t)l*NT*DIM*DIM,
                                               b1 + (size_t)l*NT*DIM);
        ffn_kernel<1><<<dim3(8, 8, 16), 256>>>(W2 + (size_t)l*NT*DIM*DIM,
                                               b2 + (size_t)l*NT*DIM);
        combine_kernel<<<UNQ, 256>>>(g_l + (size_t)l*DIM, b_l + (size_t)l*DIM);
    }
    heads_kernel<<<UNQ, 256>>>(Ws1, bs1, Ws2, bs2, Wd1, bd1, Wd2, bd2);
    scatter_kernel<<<(BATCH*11 + 255)/256, 256>>>(a, b, out);
}